// round 2
// baseline (speedup 1.0000x reference)
#include <cuda_runtime.h>
#include <cstddef>

// ---------------------------------------------------------------------------
// UNet decoder, fp32 SIMT baseline.
// Layers (B=8):
//  L1: conv3x3( up2(cat(x,enc3)) [512 ch @128x128] ) -> 128ch, *s1, relu
//  L2: conv3x3( up2(cat(out1,enc2)) [256 ch @256x256] ) -> 64ch, *s2, relu
//  L3: conv3x3( cat(out2,enc1) [128 ch @256x256] ) -> 64ch, +fb1, relu
//  L4: conv3x3( out3 [64 ch @256x256] ) -> 3ch, +fb2
// Upsample + concat are folded into the conv input gather (never materialized).
// ---------------------------------------------------------------------------

// Scratch (allocation-free rule: __device__ globals)
__device__ float g_out1[8 * 128 * 128 * 128];   //  64 MB
__device__ float g_out2[8 * 64 * 256 * 256];    // 128 MB
__device__ float g_out3[8 * 64 * 256 * 256];    // 128 MB
__device__ float g_wt1[512 * 9 * 128];          // w1 transposed to [K][OC]
__device__ float g_wt2[256 * 9 * 64];
__device__ float g_wt3[128 * 9 * 64];
__device__ float g_s1[8 * 128];
__device__ float g_s2[8 * 64];

// ---------------------------------------------------------------------------
// Weight transpose: w[OC][K] -> wt[K][OC]   (K = IC*9)
// ---------------------------------------------------------------------------
__global__ void transpose_kernel(const float* __restrict__ w,
                                 float* __restrict__ wt, int OC, int K) {
    int i = blockIdx.x * blockDim.x + threadIdx.x;
    if (i < OC * K) {
        int o = i / K;
        int k = i - o * K;
        wt[(size_t)k * OC + o] = w[i];
    }
}

// ---------------------------------------------------------------------------
// Style modulation: s[b][o] = style[b] . fcw[o] + fcb[o]   (S = 256, B = 8)
// ---------------------------------------------------------------------------
__global__ void style_mod_kernel(const float* __restrict__ style,
                                 const float* __restrict__ fcw,
                                 const float* __restrict__ fcb,
                                 float* __restrict__ s, int OC) {
    int i = blockIdx.x * blockDim.x + threadIdx.x;
    if (i >= 8 * OC) return;
    int b = i / OC;
    int o = i - b * OC;
    const float* st = style + b * 256;
    const float* w = fcw + o * 256;
    float a = fcb[o];
#pragma unroll 4
    for (int k = 0; k < 256; k++) a = fmaf(st[k], w[k], a);
    s[i] = a;
}

// ---------------------------------------------------------------------------
// Main conv3x3 kernel.
// Block: 256 threads; computes 64 output channels x 128 contiguous pixels
// (one row segment). Thread register tile: 4 oc x 8 px.
// Per-ic: smem gets a 3x130 input patch + a 9x64 weight tile (from wt[K][OC]).
// LAYER: 1 -> scale(s1)+relu, 2 -> scale(s2)+relu, 3 -> bias(fb1)+relu
// ---------------------------------------------------------------------------
template <int LAYER>
__global__ __launch_bounds__(256) void conv3x3_kernel(
    const float* __restrict__ src0, const float* __restrict__ src1,
    const float* __restrict__ wt, const float* __restrict__ sb,
    float* __restrict__ out) {
    constexpr int H = (LAYER == 1) ? 128 : 256;
    constexpr int W = H;
    constexpr int IC = (LAYER == 1) ? 512 : (LAYER == 2) ? 256 : 128;
    constexpr int OC = (LAYER == 1) ? 128 : 64;
    constexpr int SPLIT = IC / 2;                          // src0 channels
    constexpr int SH = (LAYER == 1) ? 64 : (LAYER == 2) ? 128 : 256;
    constexpr bool UP = (LAYER != 3);                      // 2x nearest upsample
    constexpr int BN = 128;                                // pixels per block
    constexpr int OCBLKS = OC / 64;
    constexpr int XBLKS = W / BN;

    const int y = blockIdx.x / XBLKS;
    const int x0 = (blockIdx.x - y * XBLKS) * BN;
    const int b = blockIdx.y / OCBLKS;
    const int ob = (blockIdx.y - b * OCBLKS) * 64;

    __shared__ __align__(16) float sW[9][64];
    __shared__ __align__(16) float sP[3][BN + 8];  // cols 0..BN+1 used

    const int t = threadIdx.x;
    const int ocg = t >> 4;   // 0..15
    const int pxg = t & 15;   // 0..15
    const int oc0 = ocg * 4;
    const int px0 = pxg * 8;

    float acc[4][8];
#pragma unroll
    for (int o = 0; o < 4; o++)
#pragma unroll
        for (int p = 0; p < 8; p++) acc[o][p] = 0.f;

    const float* s0b = src0 + (size_t)b * SPLIT * SH * SH;
    const float* s1b = src1 + (size_t)b * (IC - SPLIT) * SH * SH;

    for (int ic = 0; ic < IC; ic++) {
        // --- weight tile: wt[(ic*9+tap)*OC + ob + o] -> sW[tap][o] ---
#pragma unroll
        for (int i = t; i < 9 * 64; i += 256) {
            int tap = i >> 6;
            int o = i & 63;
            sW[tap][o] = wt[(size_t)(ic * 9 + tap) * OC + ob + o];
        }
        // --- input patch: rows y-1..y+1, cols x0-1..x0+BN ---
        const float* sp = (ic < SPLIT)
                              ? s0b + (size_t)ic * SH * SH
                              : s1b + (size_t)(ic - SPLIT) * SH * SH;
#pragma unroll
        for (int i = t; i < 3 * (BN + 2); i += 256) {
            int ky = i / (BN + 2);
            int j = i - ky * (BN + 2);
            int iy = y + ky - 1;
            int ix = x0 - 1 + j;
            float v = 0.f;
            if (iy >= 0 && iy < H && ix >= 0 && ix < W) {
                int sy = UP ? (iy >> 1) : iy;
                int sx = UP ? (ix >> 1) : ix;
                v = __ldg(sp + sy * SH + sx);
            }
            sP[ky][j] = v;
        }
        __syncthreads();

#pragma unroll
        for (int ky = 0; ky < 3; ky++) {
            // 10 contiguous patch values, vectorized (conflict-light LDS.128)
            float in[10];
            {
                const float4* r4 = reinterpret_cast<const float4*>(&sP[ky][px0]);
                float4 a = r4[0];
                float4 c = r4[1];
                const float2 e = *reinterpret_cast<const float2*>(&sP[ky][px0 + 8]);
                in[0] = a.x; in[1] = a.y; in[2] = a.z; in[3] = a.w;
                in[4] = c.x; in[5] = c.y; in[6] = c.z; in[7] = c.w;
                in[8] = e.x; in[9] = e.y;
            }
#pragma unroll
            for (int kx = 0; kx < 3; kx++) {
                const float4 wv =
                    *reinterpret_cast<const float4*>(&sW[ky * 3 + kx][oc0]);
#pragma unroll
                for (int p = 0; p < 8; p++) {
                    const float iv = in[p + kx];
                    acc[0][p] = fmaf(wv.x, iv, acc[0][p]);
                    acc[1][p] = fmaf(wv.y, iv, acc[1][p]);
                    acc[2][p] = fmaf(wv.z, iv, acc[2][p]);
                    acc[3][p] = fmaf(wv.w, iv, acc[3][p]);
                }
            }
        }
        __syncthreads();
    }

    // --- epilogue: modulate / bias, relu, store ---
#pragma unroll
    for (int o = 0; o < 4; o++) {
        const int oc = ob + oc0 + o;
        float m;
        if constexpr (LAYER == 3)
            m = sb[oc];                // bias
        else
            m = sb[b * OC + oc];       // per-(b,oc) style scale
        float* op = out + (((size_t)b * OC + oc) * H + y) * W + x0 + px0;
        float4 v0, v1;
        float r[8];
#pragma unroll
        for (int p = 0; p < 8; p++) {
            float v;
            if constexpr (LAYER == 3)
                v = acc[o][p] + m;
            else
                v = acc[o][p] * m;
            r[p] = fmaxf(v, 0.f);
        }
        v0.x = r[0]; v0.y = r[1]; v0.z = r[2]; v0.w = r[3];
        v1.x = r[4]; v1.y = r[5]; v1.z = r[6]; v1.w = r[7];
        reinterpret_cast<float4*>(op)[0] = v0;
        reinterpret_cast<float4*>(op)[1] = v1;
    }
}

// ---------------------------------------------------------------------------
// Final conv: 64 -> 3 @256x256, +fb2, no relu. One row (256 px) per block.
// ---------------------------------------------------------------------------
__global__ __launch_bounds__(256) void conv_final_kernel(
    const float* __restrict__ in, const float* __restrict__ fw2,
    const float* __restrict__ fb2, float* __restrict__ out) {
    __shared__ float sW[3 * 64 * 9];              // 1728 floats
    __shared__ __align__(16) float sP[3][264];    // cols 0..257 used

    const int y = blockIdx.x;
    const int b = blockIdx.y;
    const int t = threadIdx.x;

    for (int i = t; i < 1728; i += 256) sW[i] = fw2[i];

    float acc[3] = {0.f, 0.f, 0.f};
    const float* inb = in + (size_t)b * 64 * 65536;

    for (int ic = 0; ic < 64; ic++) {
        __syncthreads();  // sP reuse guard (also covers sW on first iter)
#pragma unroll
        for (int i = t; i < 3 * 258; i += 256) {
            int ky = i / 258;
            int j = i - ky * 258;
            int iy = y + ky - 1;
            int ix = j - 1;
            float v = 0.f;
            if (iy >= 0 && iy < 256 && ix >= 0 && ix < 256)
                v = __ldg(inb + (size_t)ic * 65536 + iy * 256 + ix);
            sP[ky][j] = v;
        }
        __syncthreads();
#pragma unroll
        for (int ky = 0; ky < 3; ky++) {
            float i0 = sP[ky][t];
            float i1 = sP[ky][t + 1];
            float i2 = sP[ky][t + 2];
#pragma unroll
            for (int o = 0; o < 3; o++) {
                const float* wp = &sW[o * 576 + ic * 9 + ky * 3];
                acc[o] = fmaf(i0, wp[0], acc[o]);
                acc[o] = fmaf(i1, wp[1], acc[o]);
                acc[o] = fmaf(i2, wp[2], acc[o]);
            }
        }
    }
#pragma unroll
    for (int o = 0; o < 3; o++)
        out[(((size_t)b * 3 + o) * 256 + y) * 256 + t] = acc[o] + fb2[o];
}

// ---------------------------------------------------------------------------
extern "C" void kernel_launch(void* const* d_in, const int* in_sizes, int n_in,
                              void* d_out, int out_size) {
    const float* x     = (const float*)d_in[0];
    const float* enc1  = (const float*)d_in[1];
    const float* enc2  = (const float*)d_in[2];
    const float* enc3  = (const float*)d_in[3];
    const float* style = (const float*)d_in[4];
    const float* w1    = (const float*)d_in[5];
    const float* fcw1  = (const float*)d_in[6];
    const float* fcb1  = (const float*)d_in[7];
    const float* w2    = (const float*)d_in[8];
    const float* fcw2  = (const float*)d_in[9];
    const float* fcb2  = (const float*)d_in[10];
    const float* fw1   = (const float*)d_in[11];
    const float* fb1   = (const float*)d_in[12];
    const float* fw2   = (const float*)d_in[13];
    const float* fb2   = (const float*)d_in[14];
    float* out = (float*)d_out;

    float *out1, *out2, *out3, *wt1, *wt2, *wt3, *s1, *s2;
    cudaGetSymbolAddress((void**)&out1, g_out1);
    cudaGetSymbolAddress((void**)&out2, g_out2);
    cudaGetSymbolAddress((void**)&out3, g_out3);
    cudaGetSymbolAddress((void**)&wt1, g_wt1);
    cudaGetSymbolAddress((void**)&wt2, g_wt2);
    cudaGetSymbolAddress((void**)&wt3, g_wt3);
    cudaGetSymbolAddress((void**)&s1, g_s1);
    cudaGetSymbolAddress((void**)&s2, g_s2);

    // prep: weight transposes + style FCs (tiny)
    transpose_kernel<<<(128 * 4608 + 255) / 256, 256>>>(w1, wt1, 128, 4608);
    transpose_kernel<<<(64 * 2304 + 255) / 256, 256>>>(w2, wt2, 64, 2304);
    transpose_kernel<<<(64 * 1152 + 255) / 256, 256>>>(fw1, wt3, 64, 1152);
    style_mod_kernel<<<4, 256>>>(style, fcw1, fcb1, s1, 128);
    style_mod_kernel<<<2, 256>>>(style, fcw2, fcb2, s2, 64);

    // L1: 128 rows x 1 xblk ; 8 batches x 2 oc-blocks
    conv3x3_kernel<1><<<dim3(128, 16), 256>>>(x, enc3, wt1, s1, out1);
    // L2: 256 rows x 2 xblk ; 8 batches x 1 oc-block
    conv3x3_kernel<2><<<dim3(512, 8), 256>>>(out1, enc2, wt2, s2, out2);
    // L3
    conv3x3_kernel<3><<<dim3(512, 8), 256>>>(out2, enc1, wt3, fb1, out3);
    // L4
    conv_final_kernel<<<dim3(256, 8), 256>>>(out3, fw2, fb2, out);
}

// round 5
// speedup vs baseline: 1.0004x; 1.0004x over previous
#include <cuda_runtime.h>
#include <cstddef>

// ---------------------------------------------------------------------------
// UNet decoder, fp32 SIMT baseline.
// Layers (B=8):
//  L1: conv3x3( up2(cat(x,enc3)) [512 ch @128x128] ) -> 128ch, *s1, relu
//  L2: conv3x3( up2(cat(out1,enc2)) [256 ch @256x256] ) -> 64ch, *s2, relu
//  L3: conv3x3( cat(out2,enc1) [128 ch @256x256] ) -> 64ch, +fb1, relu
//  L4: conv3x3( out3 [64 ch @256x256] ) -> 3ch, +fb2
// Upsample + concat are folded into the conv input gather (never materialized).
// ---------------------------------------------------------------------------

// Scratch (allocation-free rule: __device__ globals)
__device__ float g_out1[8 * 128 * 128 * 128];   //  64 MB
__device__ float g_out2[8 * 64 * 256 * 256];    // 128 MB
__device__ float g_out3[8 * 64 * 256 * 256];    // 128 MB
__device__ float g_wt1[512 * 9 * 128];          // w1 transposed to [K][OC]
__device__ float g_wt2[256 * 9 * 64];
__device__ float g_wt3[128 * 9 * 64];
__device__ float g_s1[8 * 128];
__device__ float g_s2[8 * 64];

// ---------------------------------------------------------------------------
// Weight transpose: w[OC][K] -> wt[K][OC]   (K = IC*9)
// ---------------------------------------------------------------------------
__global__ void transpose_kernel(const float* __restrict__ w,
                                 float* __restrict__ wt, int OC, int K) {
    int i = blockIdx.x * blockDim.x + threadIdx.x;
    if (i < OC * K) {
        int o = i / K;
        int k = i - o * K;
        wt[(size_t)k * OC + o] = w[i];
    }
}

// ---------------------------------------------------------------------------
// Style modulation: s[b][o] = style[b] . fcw[o] + fcb[o]   (S = 256, B = 8)
// ---------------------------------------------------------------------------
__global__ void style_mod_kernel(const float* __restrict__ style,
                                 const float* __restrict__ fcw,
                                 const float* __restrict__ fcb,
                                 float* __restrict__ s, int OC) {
    int i = blockIdx.x * blockDim.x + threadIdx.x;
    if (i >= 8 * OC) return;
    int b = i / OC;
    int o = i - b * OC;
    const float* st = style + b * 256;
    const float* w = fcw + o * 256;
    float a = fcb[o];
#pragma unroll 4
    for (int k = 0; k < 256; k++) a = fmaf(st[k], w[k], a);
    s[i] = a;
}

// ---------------------------------------------------------------------------
// Main conv3x3 kernel.
// Block: 256 threads; computes 64 output channels x 128 contiguous pixels
// (one row segment). Thread register tile: 4 oc x 8 px.
// Per-ic: smem gets a 3x130 input patch + a 9x64 weight tile (from wt[K][OC]).
// LAYER: 1 -> scale(s1)+relu, 2 -> scale(s2)+relu, 3 -> bias(fb1)+relu
// ---------------------------------------------------------------------------
template <int LAYER>
__global__ __launch_bounds__(256) void conv3x3_kernel(
    const float* __restrict__ src0, const float* __restrict__ src1,
    const float* __restrict__ wt, const float* __restrict__ sb,
    float* __restrict__ out) {
    constexpr int H = (LAYER == 1) ? 128 : 256;
    constexpr int W = H;
    constexpr int IC = (LAYER == 1) ? 512 : (LAYER == 2) ? 256 : 128;
    constexpr int OC = (LAYER == 1) ? 128 : 64;
    constexpr int SPLIT = IC / 2;                          // src0 channels
    constexpr int SH = (LAYER == 1) ? 64 : (LAYER == 2) ? 128 : 256;
    constexpr bool UP = (LAYER != 3);                      // 2x nearest upsample
    constexpr int BN = 128;                                // pixels per block
    constexpr int OCBLKS = OC / 64;
    constexpr int XBLKS = W / BN;

    const int y = blockIdx.x / XBLKS;
    const int x0 = (blockIdx.x - y * XBLKS) * BN;
    const int b = blockIdx.y / OCBLKS;
    const int ob = (blockIdx.y - b * OCBLKS) * 64;

    __shared__ __align__(16) float sW[9][64];
    __shared__ __align__(16) float sP[3][BN + 8];  // cols 0..BN+1 used

    const int t = threadIdx.x;
    const int ocg = t >> 4;   // 0..15
    const int pxg = t & 15;   // 0..15
    const int oc0 = ocg * 4;
    const int px0 = pxg * 8;

    float acc[4][8];
#pragma unroll
    for (int o = 0; o < 4; o++)
#pragma unroll
        for (int p = 0; p < 8; p++) acc[o][p] = 0.f;

    const float* s0b = src0 + (size_t)b * SPLIT * SH * SH;
    const float* s1b = src1 + (size_t)b * (IC - SPLIT) * SH * SH;

    for (int ic = 0; ic < IC; ic++) {
        // --- weight tile: wt[(ic*9+tap)*OC + ob + o] -> sW[tap][o] ---
#pragma unroll
        for (int i = t; i < 9 * 64; i += 256) {
            int tap = i >> 6;
            int o = i & 63;
            sW[tap][o] = wt[(size_t)(ic * 9 + tap) * OC + ob + o];
        }
        // --- input patch: rows y-1..y+1, cols x0-1..x0+BN ---
        const float* sp = (ic < SPLIT)
                              ? s0b + (size_t)ic * SH * SH
                              : s1b + (size_t)(ic - SPLIT) * SH * SH;
#pragma unroll
        for (int i = t; i < 3 * (BN + 2); i += 256) {
            int ky = i / (BN + 2);
            int j = i - ky * (BN + 2);
            int iy = y + ky - 1;
            int ix = x0 - 1 + j;
            float v = 0.f;
            if (iy >= 0 && iy < H && ix >= 0 && ix < W) {
                int sy = UP ? (iy >> 1) : iy;
                int sx = UP ? (ix >> 1) : ix;
                v = __ldg(sp + sy * SH + sx);
            }
            sP[ky][j] = v;
        }
        __syncthreads();

#pragma unroll
        for (int ky = 0; ky < 3; ky++) {
            // 10 contiguous patch values, vectorized (conflict-light LDS.128)
            float in[10];
            {
                const float4* r4 = reinterpret_cast<const float4*>(&sP[ky][px0]);
                float4 a = r4[0];
                float4 c = r4[1];
                const float2 e = *reinterpret_cast<const float2*>(&sP[ky][px0 + 8]);
                in[0] = a.x; in[1] = a.y; in[2] = a.z; in[3] = a.w;
                in[4] = c.x; in[5] = c.y; in[6] = c.z; in[7] = c.w;
                in[8] = e.x; in[9] = e.y;
            }
#pragma unroll
            for (int kx = 0; kx < 3; kx++) {
                const float4 wv =
                    *reinterpret_cast<const float4*>(&sW[ky * 3 + kx][oc0]);
#pragma unroll
                for (int p = 0; p < 8; p++) {
                    const float iv = in[p + kx];
                    acc[0][p] = fmaf(wv.x, iv, acc[0][p]);
                    acc[1][p] = fmaf(wv.y, iv, acc[1][p]);
                    acc[2][p] = fmaf(wv.z, iv, acc[2][p]);
                    acc[3][p] = fmaf(wv.w, iv, acc[3][p]);
                }
            }
        }
        __syncthreads();
    }

    // --- epilogue: modulate / bias, relu, store ---
#pragma unroll
    for (int o = 0; o < 4; o++) {
        const int oc = ob + oc0 + o;
        float m;
        if constexpr (LAYER == 3)
            m = sb[oc];                // bias
        else
            m = sb[b * OC + oc];       // per-(b,oc) style scale
        float* op = out + (((size_t)b * OC + oc) * H + y) * W + x0 + px0;
        float4 v0, v1;
        float r[8];
#pragma unroll
        for (int p = 0; p < 8; p++) {
            float v;
            if constexpr (LAYER == 3)
                v = acc[o][p] + m;
            else
                v = acc[o][p] * m;
            r[p] = fmaxf(v, 0.f);
        }
        v0.x = r[0]; v0.y = r[1]; v0.z = r[2]; v0.w = r[3];
        v1.x = r[4]; v1.y = r[5]; v1.z = r[6]; v1.w = r[7];
        reinterpret_cast<float4*>(op)[0] = v0;
        reinterpret_cast<float4*>(op)[1] = v1;
    }
}

// ---------------------------------------------------------------------------
// Final conv: 64 -> 3 @256x256, +fb2, no relu. One row (256 px) per block.
// ---------------------------------------------------------------------------
__global__ __launch_bounds__(256) void conv_final_kernel(
    const float* __restrict__ in, const float* __restrict__ fw2,
    const float* __restrict__ fb2, float* __restrict__ out) {
    __shared__ float sW[3 * 64 * 9];              // 1728 floats
    __shared__ __align__(16) float sP[3][264];    // cols 0..257 used

    const int y = blockIdx.x;
    const int b = blockIdx.y;
    const int t = threadIdx.x;

    for (int i = t; i < 1728; i += 256) sW[i] = fw2[i];

    float acc[3] = {0.f, 0.f, 0.f};
    const float* inb = in + (size_t)b * 64 * 65536;

    for (int ic = 0; ic < 64; ic++) {
        __syncthreads();  // sP reuse guard (also covers sW on first iter)
#pragma unroll
        for (int i = t; i < 3 * 258; i += 256) {
            int ky = i / 258;
            int j = i - ky * 258;
            int iy = y + ky - 1;
            int ix = j - 1;
            float v = 0.f;
            if (iy >= 0 && iy < 256 && ix >= 0 && ix < 256)
                v = __ldg(inb + (size_t)ic * 65536 + iy * 256 + ix);
            sP[ky][j] = v;
        }
        __syncthreads();
#pragma unroll
        for (int ky = 0; ky < 3; ky++) {
            float i0 = sP[ky][t];
            float i1 = sP[ky][t + 1];
            float i2 = sP[ky][t + 2];
#pragma unroll
            for (int o = 0; o < 3; o++) {
                const float* wp = &sW[o * 576 + ic * 9 + ky * 3];
                acc[o] = fmaf(i0, wp[0], acc[o]);
                acc[o] = fmaf(i1, wp[1], acc[o]);
                acc[o] = fmaf(i2, wp[2], acc[o]);
            }
        }
    }
#pragma unroll
    for (int o = 0; o < 3; o++)
        out[(((size_t)b * 3 + o) * 256 + y) * 256 + t] = acc[o] + fb2[o];
}

// ---------------------------------------------------------------------------
extern "C" void kernel_launch(void* const* d_in, const int* in_sizes, int n_in,
                              void* d_out, int out_size) {
    const float* x     = (const float*)d_in[0];
    const float* enc1  = (const float*)d_in[1];
    const float* enc2  = (const float*)d_in[2];
    const float* enc3  = (const float*)d_in[3];
    const float* style = (const float*)d_in[4];
    const float* w1    = (const float*)d_in[5];
    const float* fcw1  = (const float*)d_in[6];
    const float* fcb1  = (const float*)d_in[7];
    const float* w2    = (const float*)d_in[8];
    const float* fcw2  = (const float*)d_in[9];
    const float* fcb2  = (const float*)d_in[10];
    const float* fw1   = (const float*)d_in[11];
    const float* fb1   = (const float*)d_in[12];
    const float* fw2   = (const float*)d_in[13];
    const float* fb2   = (const float*)d_in[14];
    float* out = (float*)d_out;

    float *out1, *out2, *out3, *wt1, *wt2, *wt3, *s1, *s2;
    cudaGetSymbolAddress((void**)&out1, g_out1);
    cudaGetSymbolAddress((void**)&out2, g_out2);
    cudaGetSymbolAddress((void**)&out3, g_out3);
    cudaGetSymbolAddress((void**)&wt1, g_wt1);
    cudaGetSymbolAddress((void**)&wt2, g_wt2);
    cudaGetSymbolAddress((void**)&wt3, g_wt3);
    cudaGetSymbolAddress((void**)&s1, g_s1);
    cudaGetSymbolAddress((void**)&s2, g_s2);

    // prep: weight transposes + style FCs (tiny)
    transpose_kernel<<<(128 * 4608 + 255) / 256, 256>>>(w1, wt1, 128, 4608);
    transpose_kernel<<<(64 * 2304 + 255) / 256, 256>>>(w2, wt2, 64, 2304);
    transpose_kernel<<<(64 * 1152 + 255) / 256, 256>>>(fw1, wt3, 64, 1152);
    style_mod_kernel<<<4, 256>>>(style, fcw1, fcb1, s1, 128);
    style_mod_kernel<<<2, 256>>>(style, fcw2, fcb2, s2, 64);

    // L1: 128 rows x 1 xblk ; 8 batches x 2 oc-blocks
    conv3x3_kernel<1><<<dim3(128, 16), 256>>>(x, enc3, wt1, s1, out1);
    // L2: 256 rows x 2 xblk ; 8 batches x 1 oc-block
    conv3x3_kernel<2><<<dim3(512, 8), 256>>>(out1, enc2, wt2, s2, out2);
    // L3
    conv3x3_kernel<3><<<dim3(512, 8), 256>>>(out2, enc1, wt3, fb1, out3);
    // L4
    conv_final_kernel<<<dim3(256, 8), 256>>>(out3, fw2, fb2, out);
}

// round 7
// speedup vs baseline: 2.8885x; 2.8873x over previous
#include <cuda_runtime.h>
#include <cstdint>
#include <cstddef>

// ===========================================================================
// UNet decoder via warp-level tf32 mma.sync (HMMA on the tensor pipe).
// All activations NHWC fp32; upsample/concat materialized or fused into conv
// epilogues. Conv = implicit GEMM, CTA = 128px x 64oc, warp tile 32x32,
// m16n8k8 tf32 fragments composed directly from a shifted NHWC smem slab.
// ===========================================================================

__device__ float g_A1[8 * 128 * 128 * 512];  // up2(cat(x,enc3))        268MB
__device__ float g_A2[8 * 256 * 256 * 256];  // [out1up | enc2up]       537MB
__device__ float g_A3[8 * 256 * 256 * 128];  // [out2 | enc1]           268MB
__device__ float g_O3[8 * 256 * 256 * 64];   // out3                    134MB
__device__ float g_w1[9 * 512 * 128];        // gw[ky][kx][ic][oc] tf32-rounded
__device__ float g_w2[9 * 256 * 64];
__device__ float g_w3[9 * 128 * 64];
__device__ float g_w4[9 * 64 * 64];          // oc padded 3 -> 64
__device__ float g_s1[8 * 128];
__device__ float g_s2[8 * 64];

__device__ __forceinline__ uint32_t tf32r(float x) {
    uint32_t u;
    asm("cvt.rna.tf32.f32 %0, %1;" : "=r"(u) : "f"(x));
    return u;
}

__device__ __forceinline__ void mma8(float* c, const uint32_t* a, uint32_t b0,
                                     uint32_t b1) {
    asm volatile(
        "mma.sync.aligned.m16n8k8.row.col.f32.tf32.tf32.f32 "
        "{%0,%1,%2,%3}, {%4,%5,%6,%7}, {%8,%9}, {%0,%1,%2,%3};"
        : "+f"(c[0]), "+f"(c[1]), "+f"(c[2]), "+f"(c[3])
        : "r"(a[0]), "r"(a[1]), "r"(a[2]), "r"(a[3]), "r"(b0), "r"(b1));
}

// ---------------------------------------------------------------------------
// NCHW -> NHWC (+ optional nearest 2x upsample). Tile: 64 ch x 64 out-px.
// ---------------------------------------------------------------------------
template <bool UP>
__global__ __launch_bounds__(256) void nchw2nhwc(const float* __restrict__ src,
                                                 float* __restrict__ dst,
                                                 int Csrc, int Hsrc, int Wout,
                                                 int Crow, int coff) {
    constexpr int SXT = UP ? 32 : 64;
    __shared__ float sm[64][SXT + 1];
    const int xtiles = Wout >> 6;
    const int xt = blockIdx.x % xtiles;
    const int ct = blockIdx.x / xtiles;
    const int y = blockIdx.y, b = blockIdx.z;
    const int sy = UP ? (y >> 1) : y;
    const int t = threadIdx.x;

    const float* sp =
        src + ((size_t)(b * Csrc + ct * 64) * Hsrc + sy) * Hsrc + xt * SXT;
    for (int i = t; i < 64 * SXT / 4; i += 256) {
        int c = i / (SXT / 4), q = i % (SXT / 4);
        float4 v = *(const float4*)(sp + (size_t)c * Hsrc * Hsrc + q * 4);
        sm[c][q * 4 + 0] = v.x;
        sm[c][q * 4 + 1] = v.y;
        sm[c][q * 4 + 2] = v.z;
        sm[c][q * 4 + 3] = v.w;
    }
    __syncthreads();
    float* dp = dst + (((size_t)b * Wout + y) * Wout + xt * 64) * Crow + coff +
                ct * 64;
    for (int i = t; i < 1024; i += 256) {
        int x = i >> 4, cq = i & 15;
        int sx = UP ? (x >> 1) : x;
        float4 v = make_float4(sm[cq * 4 + 0][sx], sm[cq * 4 + 1][sx],
                               sm[cq * 4 + 2][sx], sm[cq * 4 + 3][sx]);
        *(float4*)(dp + (size_t)x * Crow + cq * 4) = v;
    }
}

// ---------------------------------------------------------------------------
// Weights: w[oc][ic][ky][kx] -> gw[((ky*3+kx)*IC+ic)*OCp + oc], tf32-rounded.
// ---------------------------------------------------------------------------
__global__ void wtrans(const float* __restrict__ w, float* __restrict__ gw,
                       int OCsrc, int OCp, int IC) {
    int i = blockIdx.x * blockDim.x + threadIdx.x;
    if (i >= 9 * IC * OCp) return;
    int oc = i % OCp;
    int r = i / OCp;
    int ic = r % IC;
    r /= IC;
    int kx = r % 3, ky = r / 3;
    float v = (oc < OCsrc) ? w[((size_t)(oc * IC + ic) * 3 + ky) * 3 + kx] : 0.f;
    gw[i] = __uint_as_float(tf32r(v));
}

__global__ void style_mod(const float* __restrict__ style,
                          const float* __restrict__ fcw,
                          const float* __restrict__ fcb, float* __restrict__ s,
                          int OC) {
    int i = blockIdx.x * blockDim.x + threadIdx.x;
    if (i >= 8 * OC) return;
    int b = i / OC, o = i - b * OC;
    const float* st = style + b * 256;
    const float* wp = fcw + o * 256;
    float a = fcb[o];
#pragma unroll 4
    for (int k = 0; k < 256; k++) a = fmaf(st[k], wp[k], a);
    s[i] = a;
}

// ---------------------------------------------------------------------------
// Implicit-GEMM conv3x3.  LAYER: 1 512->128 @128^2 (scale,relu, 2x-dup -> A2)
//                                2 256->64  @256^2 (scale,relu -> A3 ch0-63)
//                                3 128->64  @256^2 (+fb1,relu -> O3)
//                                4  64->64p @256^2 (+fb2, oc<3 -> NCHW out)
// ---------------------------------------------------------------------------
template <int LAYER>
__global__ __launch_bounds__(256) void conv_mma(const float* __restrict__ in,
                                                const float* __restrict__ gw,
                                                const float* __restrict__ sb,
                                                float* __restrict__ out) {
    constexpr int H = (LAYER == 1) ? 128 : 256;
    constexpr int W = H;
    constexpr int IC = (LAYER == 1) ? 512 : (LAYER == 2) ? 256
                       : (LAYER == 3) ? 128 : 64;
    constexpr int OCp = (LAYER == 1) ? 128 : 64;  // oc stride in gw
    constexpr int OCB = OCp / 64;
    constexpr int XB = W / 128;

    __shared__ uint32_t sA[130][36];      // [px(+1)][32 ch], stride 36
    __shared__ uint32_t sB[3][32][72];    // [kx][ic][64 oc], stride 72

    const int t = threadIdx.x, lane = t & 31, wid = t >> 5;
    const int g = lane >> 2, tig = lane & 3;
    const int wm = wid >> 1, wn = wid & 1;
    const int y = blockIdx.x / XB, x0 = (blockIdx.x % XB) * 128;
    const int b = blockIdx.y / OCB, ob = (blockIdx.y % OCB) * 64;

    float acc[2][4][4];
#pragma unroll
    for (int mt = 0; mt < 2; mt++)
#pragma unroll
        for (int nt = 0; nt < 4; nt++)
#pragma unroll
            for (int k = 0; k < 4; k++) acc[mt][nt][k] = 0.f;

    const float* inb = in + (size_t)b * H * W * IC;

    for (int ic0 = 0; ic0 < IC; ic0 += 32) {
        for (int ky = 0; ky < 3; ky++) {
            __syncthreads();
            // weight tile
            for (int i = t; i < 3 * 32 * 64; i += 256) {
                int oc = i & 63, r = i >> 6;
                int ic = r & 31, kx = r >> 5;
                sB[kx][ic][oc] = __float_as_uint(
                    gw[(size_t)((ky * 3 + kx) * IC + ic0 + ic) * OCp + ob + oc]);
            }
            // activation slab: row y+ky-1, x0-1..x0+128, 32 channels
            const int gy = y + ky - 1;
            for (int i = t; i < 130 * 8; i += 256) {
                int px = i >> 3, q = i & 7;
                int gx = x0 - 1 + px;
                uint32_t v0 = 0, v1 = 0, v2 = 0, v3 = 0;
                if (gy >= 0 && gy < H && gx >= 0 && gx < W) {
                    float4 f = *(const float4*)(inb + ((size_t)gy * W + gx) * IC +
                                                ic0 + q * 4);
                    v0 = tf32r(f.x); v1 = tf32r(f.y);
                    v2 = tf32r(f.z); v3 = tf32r(f.w);
                }
                uint32_t* d = &sA[px][q * 4];
                d[0] = v0; d[1] = v1; d[2] = v2; d[3] = v3;
            }
            __syncthreads();
#pragma unroll
            for (int kx = 0; kx < 3; kx++) {
#pragma unroll
                for (int ks = 0; ks < 4; ks++) {
                    const int kc = ks * 8;
                    uint32_t a[2][4];
#pragma unroll
                    for (int mt = 0; mt < 2; mt++) {
                        const int r0 = wm * 32 + mt * 16 + g + kx;
                        a[mt][0] = sA[r0][kc + tig];
                        a[mt][1] = sA[r0 + 8][kc + tig];
                        a[mt][2] = sA[r0][kc + tig + 4];
                        a[mt][3] = sA[r0 + 8][kc + tig + 4];
                    }
#pragma unroll
                    for (int nt = 0; nt < 4; nt++) {
                        const uint32_t b0 = sB[kx][kc + tig][wn * 32 + nt * 8 + g];
                        const uint32_t b1 =
                            sB[kx][kc + tig + 4][wn * 32 + nt * 8 + g];
                        mma8(acc[0][nt], a[0], b0, b1);
                        mma8(acc[1][nt], a[1], b0, b1);
                    }
                }
            }
        }
    }

    // ---------------- epilogue ----------------
#pragma unroll
    for (int mt = 0; mt < 2; mt++) {
#pragma unroll
        for (int nt = 0; nt < 4; nt++) {
            const int oc = ob + wn * 32 + nt * 8 + tig * 2;
#pragma unroll
            for (int h = 0; h < 2; h++) {  // c-rows: x and x+8
                const int x = x0 + wm * 32 + mt * 16 + g + h * 8;
                float v0 = acc[mt][nt][h * 2 + 0];
                float v1 = acc[mt][nt][h * 2 + 1];
                if constexpr (LAYER == 1) {
                    v0 = fmaxf(v0 * sb[b * 128 + oc], 0.f);
                    v1 = fmaxf(v1 * sb[b * 128 + oc + 1], 0.f);
                    float2 pv = make_float2(v0, v1);
#pragma unroll
                    for (int dy = 0; dy < 2; dy++)
#pragma unroll
                        for (int dx = 0; dx < 2; dx++)
                            *(float2*)(out +
                                       (((size_t)b * 256 + 2 * y + dy) * 256 +
                                        2 * x + dx) *
                                           256 +
                                       oc) = pv;
                } else if constexpr (LAYER == 2) {
                    v0 = fmaxf(v0 * sb[b * 64 + oc], 0.f);
                    v1 = fmaxf(v1 * sb[b * 64 + oc + 1], 0.f);
                    *(float2*)(out + (((size_t)b * 256 + y) * 256 + x) * 128 +
                               oc) = make_float2(v0, v1);
                } else if constexpr (LAYER == 3) {
                    v0 = fmaxf(v0 + sb[oc], 0.f);
                    v1 = fmaxf(v1 + sb[oc + 1], 0.f);
                    *(float2*)(out + (((size_t)b * 256 + y) * 256 + x) * 64 +
                               oc) = make_float2(v0, v1);
                } else {
                    if (oc < 3)
                        out[(((size_t)b * 3 + oc) * 256 + y) * 256 + x] =
                            v0 + sb[oc];
                    if (oc + 1 < 3)
                        out[(((size_t)b * 3 + oc + 1) * 256 + y) * 256 + x] =
                            v1 + sb[oc + 1];
                }
            }
        }
    }
}

// ---------------------------------------------------------------------------
extern "C" void kernel_launch(void* const* d_in, const int* in_sizes, int n_in,
                              void* d_out, int out_size) {
    const float* x     = (const float*)d_in[0];
    const float* enc1  = (const float*)d_in[1];
    const float* enc2  = (const float*)d_in[2];
    const float* enc3  = (const float*)d_in[3];
    const float* style = (const float*)d_in[4];
    const float* w1    = (const float*)d_in[5];
    const float* fcw1  = (const float*)d_in[6];
    const float* fcb1  = (const float*)d_in[7];
    const float* w2    = (const float*)d_in[8];
    const float* fcw2  = (const float*)d_in[9];
    const float* fcb2  = (const float*)d_in[10];
    const float* fw1   = (const float*)d_in[11];
    const float* fb1   = (const float*)d_in[12];
    const float* fw2   = (const float*)d_in[13];
    const float* fb2   = (const float*)d_in[14];
    float* out = (float*)d_out;

    float *A1, *A2, *A3, *O3, *gw1, *gw2, *gw3, *gw4, *s1, *s2;
    cudaGetSymbolAddress((void**)&A1, g_A1);
    cudaGetSymbolAddress((void**)&A2, g_A2);
    cudaGetSymbolAddress((void**)&A3, g_A3);
    cudaGetSymbolAddress((void**)&O3, g_O3);
    cudaGetSymbolAddress((void**)&gw1, g_w1);
    cudaGetSymbolAddress((void**)&gw2, g_w2);
    cudaGetSymbolAddress((void**)&gw3, g_w3);
    cudaGetSymbolAddress((void**)&gw4, g_w4);
    cudaGetSymbolAddress((void**)&s1, g_s1);
    cudaGetSymbolAddress((void**)&s2, g_s2);

    // weight + style prep (tiny)
    wtrans<<<(9 * 512 * 128 + 255) / 256, 256>>>(w1, gw1, 128, 128, 512);
    wtrans<<<(9 * 256 * 64 + 255) / 256, 256>>>(w2, gw2, 64, 64, 256);
    wtrans<<<(9 * 128 * 64 + 255) / 256, 256>>>(fw1, gw3, 64, 64, 128);
    wtrans<<<(9 * 64 * 64 + 255) / 256, 256>>>(fw2, gw4, 3, 64, 64);
    style_mod<<<4, 256>>>(style, fcw1, fcb1, s1, 128);
    style_mod<<<2, 256>>>(style, fcw2, fcb2, s2, 64);

    // NHWC conversions (+up2): A1 = [x | enc3] up2; A2 ch128+ = enc2 up2;
    // A3 ch64+ = enc1
    nchw2nhwc<true><<<dim3(2 * 4, 128, 8), 256>>>(x, A1, 256, 64, 128, 512, 0);
    nchw2nhwc<true><<<dim3(2 * 4, 128, 8), 256>>>(enc3, A1, 256, 64, 128, 512,
                                                  256);
    nchw2nhwc<true><<<dim3(4 * 2, 256, 8), 256>>>(enc2, A2, 128, 128, 256, 256,
                                                  128);
    nchw2nhwc<false><<<dim3(4 * 1, 256, 8), 256>>>(enc1, A3, 64, 256, 256, 128,
                                                   64);

    // convs (conv1 writes up2'd result into A2 ch0-127; conv2 into A3 ch0-63)
    conv_mma<1><<<dim3(128, 16), 256>>>(A1, gw1, s1, A2);
    conv_mma<2><<<dim3(512, 8), 256>>>(A2, gw2, s2, A3);
    conv_mma<3><<<dim3(512, 8), 256>>>(A3, gw3, fb1, O3);
    conv_mma<4><<<dim3(512, 8), 256>>>(O3, gw4, fb2, out);
}